// round 5
// baseline (speedup 1.0000x reference)
#include <cuda_runtime.h>
#include <cuda_bf16.h>
#include <math.h>
#include <stdint.h>

#define NB 8
#define CD 128
#define KC 64
#define HD 16
#define WD 900
#define HW 14400
#define NCH 90
#define NW 30
#define NR 240
#define NRP 256
#define OD 256
#define KSP 16
#define KD 8192

__device__ float g_cwx[(size_t)NB * NCH * KC * CD];       // (n,j,k,c)
__device__ float g_ca[(size_t)NB * NCH * KC];             // (n,j,k)
__device__ unsigned short g_vh[(size_t)NRP * KD];         // vlad bf16 hi (rows>=240 stay 0)
__device__ unsigned short g_vl[(size_t)NRP * KD];
__device__ unsigned short g_wh[(size_t)OD * KD];
__device__ unsigned short g_wl[(size_t)OD * KD];
__device__ float g_part[(size_t)KSP * NR * OD];

// ---------------------------------------------------------------------------
// helpers
// ---------------------------------------------------------------------------
__device__ __forceinline__ uint32_t smem_u32(const void* p) {
    uint32_t a;
    asm("{ .reg .u64 t; cvta.to.shared.u64 t, %1; cvt.u32.u64 %0, t; }"
        : "=r"(a) : "l"(p));
    return a;
}
__device__ __forceinline__ void ldm_x4(uint32_t (&r)[4], uint32_t addr) {
    asm volatile("ldmatrix.sync.aligned.m8n8.x4.shared.b16 {%0,%1,%2,%3}, [%4];"
                 : "=r"(r[0]), "=r"(r[1]), "=r"(r[2]), "=r"(r[3]) : "r"(addr));
}
__device__ __forceinline__ void ldm_x4t(uint32_t (&r)[4], uint32_t addr) {
    asm volatile("ldmatrix.sync.aligned.m8n8.x4.trans.shared.b16 {%0,%1,%2,%3}, [%4];"
                 : "=r"(r[0]), "=r"(r[1]), "=r"(r[2]), "=r"(r[3]) : "r"(addr));
}
__device__ __forceinline__ void mma16816(float (&d)[4], const uint32_t (&a)[4],
                                         const uint32_t b0, const uint32_t b1) {
    asm volatile(
        "mma.sync.aligned.m16n8k16.row.col.f32.bf16.bf16.f32 "
        "{%0,%1,%2,%3}, {%4,%5,%6,%7}, {%8,%9}, {%0,%1,%2,%3};"
        : "+f"(d[0]), "+f"(d[1]), "+f"(d[2]), "+f"(d[3])
        : "r"(a[0]), "r"(a[1]), "r"(a[2]), "r"(a[3]), "r"(b0), "r"(b1));
}
__device__ __forceinline__ void bsplit(float v, unsigned short& h, unsigned short& l) {
    __nv_bfloat16 bh = __float2bfloat16(v);
    __nv_bfloat16 bl = __float2bfloat16(v - __bfloat162float(bh));
    h = __bfloat16_as_ushort(bh);
    l = __bfloat16_as_ushort(bl);
}

// ---------------------------------------------------------------------------
// Kernel W: convert mlp_w to bf16 hi/lo
// ---------------------------------------------------------------------------
__global__ __launch_bounds__(256) void kW(const float* __restrict__ mw) {
    size_t base = ((size_t)blockIdx.x * 256 + threadIdx.x) * 8;
    float4 v0 = *(const float4*)(mw + base);
    float4 v1 = *(const float4*)(mw + base + 4);
    float vv[8] = {v0.x, v0.y, v0.z, v0.w, v1.x, v1.y, v1.z, v1.w};
    unsigned short h[8], l[8];
#pragma unroll
    for (int i = 0; i < 8; i++) bsplit(vv[i], h[i], l[i]);
    *(ushort4*)(g_wh + base)     = make_ushort4(h[0], h[1], h[2], h[3]);
    *(ushort4*)(g_wh + base + 4) = make_ushort4(h[4], h[5], h[6], h[7]);
    *(ushort4*)(g_wl + base)     = make_ushort4(l[0], l[1], l[2], l[3]);
    *(ushort4*)(g_wl + base + 4) = make_ushort4(l[4], l[5], l[6], l[7]);
}

// ---------------------------------------------------------------------------
// Kernel F (fused assignment + chunk GEMM), one block per (n, chunk j).
// Stage x[c][q] once (2 stages of 80 q); logits via mma (B from x via
// ldmatrix.trans), softmax over k in fragments, a -> smem, chunk GEMM
// D[k,c] = a @ x^T from the same x tile. Outputs g_cwx (k,c) and g_ca.
// ---------------------------------------------------------------------------
#define F_RS   88
#define F_WRS  136
#define F_WH   0
#define F_WL   17408
#define F_XH   34816
#define F_XL   57344
#define F_AH   79872
#define F_AL   91136
#define F_CB   102400
#define F_RED  102656   // float[4][80]
#define F_CA   103936   // float[2][64]
#define F_SMEM 104448

__global__ __launch_bounds__(256, 2) void kF(const float* __restrict__ x,
                                             const float* __restrict__ cw,
                                             const float* __restrict__ cb) {
    extern __shared__ char smem[];
    const uint32_t sb = smem_u32(smem);
    unsigned short* sWH = (unsigned short*)(smem + F_WH);
    unsigned short* sWL = (unsigned short*)(smem + F_WL);
    unsigned short* sXH = (unsigned short*)(smem + F_XH);
    unsigned short* sXL = (unsigned short*)(smem + F_XL);
    unsigned short* sAH = (unsigned short*)(smem + F_AH);
    unsigned short* sAL = (unsigned short*)(smem + F_AL);
    float* cbs  = (float*)(smem + F_CB);
    float* sred = (float*)(smem + F_RED);
    float* sCA  = (float*)(smem + F_CA);

    const int tid = threadIdx.x;
    const int wid = tid >> 5;
    const int L   = tid & 31;
    const int n = blockIdx.x / NCH;
    const int j = blockIdx.x % NCH;

    const int wk = wid & 3;    // k block of 16 (both phases)
    const int qh = wid >> 2;   // logits: q half (40)
    const int wc = wid >> 2;   // gemm2: c half (64)

    const int a_row = (L & 7) + ((L >> 3) & 1) * 8;
    const int a_ch  = (L >> 4) * 8;
    const int b_row = (L & 7) + (L >> 4) * 8;
    const int b_ch  = ((L >> 3) & 1) * 8;

    // stage W hi/lo
    {
        int k = tid >> 2, cg = (tid & 3) * 32;
        const float* wp = cw + k * CD + cg;
#pragma unroll
        for (int it = 0; it < 8; ++it) {
            float4 v = *(const float4*)(wp + it * 4);
            unsigned short h[4], l[4];
            bsplit(v.x, h[0], l[0]); bsplit(v.y, h[1], l[1]);
            bsplit(v.z, h[2], l[2]); bsplit(v.w, h[3], l[3]);
            *(ushort4*)&sWH[k * F_WRS + cg + it * 4] = make_ushort4(h[0], h[1], h[2], h[3]);
            *(ushort4*)&sWL[k * F_WRS + cg + it * 4] = make_ushort4(l[0], l[1], l[2], l[3]);
        }
    }
    if (tid < 64) cbs[tid] = cb[tid];
    if (tid < 128) sCA[tid] = 0.f;

    float acc2[8][4];
#pragma unroll
    for (int ni = 0; ni < 8; ni++)
#pragma unroll
        for (int e = 0; e < 4; e++) acc2[ni][e] = 0.f;

    const int row0 = wk * 16 + (L >> 2);
    const int row1 = row0 + 8;

#pragma unroll
    for (int s = 0; s < 2; ++s) {
        // ---- stage x tile [c][q80] hi/lo ----
#pragma unroll
        for (int it = 0; it < 4; ++it) {
            int p = tid + it * 256;
            int c = p >> 3, h8 = p & 7;
            int h = s * 8 + h8;
            const float* gp = x + (size_t)n * CD * HW + (size_t)c * HW +
                              (size_t)h * WD + (size_t)j * 10;
            int colb = c * F_RS + h8 * 10;
#pragma unroll
            for (int w2 = 0; w2 < 5; ++w2) {
                float2 v = *(const float2*)(gp + w2 * 2);
                unsigned short h0, l0, h1, l1;
                bsplit(v.x, h0, l0);
                bsplit(v.y, h1, l1);
                *(uint*)&sXH[colb + w2 * 2] = (uint)h0 | ((uint)h1 << 16);
                *(uint*)&sXL[colb + w2 * 2] = (uint)l0 | ((uint)l1 << 16);
            }
        }
        __syncthreads();

        // ---- logits mma: D[k16][q40] per warp ----
        float aL[5][4];
#pragma unroll
        for (int ni = 0; ni < 5; ni++)
#pragma unroll
            for (int e = 0; e < 4; e++) aL[ni][e] = 0.f;

#pragma unroll
        for (int kc = 0; kc < 8; ++kc) {
            uint32_t wh[4], wl[4];
            uint32_t offw = (uint32_t)((wk * 16 + a_row) * F_WRS + kc * 16 + a_ch) * 2;
            ldm_x4(wh, sb + F_WH + offw);
            ldm_x4(wl, sb + F_WL + offw);
            uint32_t bxh[3][4], bxl[3][4];
#pragma unroll
            for (int t3 = 0; t3 < 3; ++t3) {
                uint32_t offx = (uint32_t)((kc * 16 + a_row) * F_RS + qh * 40 + t3 * 16 + a_ch) * 2;
                ldm_x4t(bxh[t3], sb + F_XH + offx);
                ldm_x4t(bxl[t3], sb + F_XL + offx);
            }
#pragma unroll
            for (int ni = 0; ni < 5; ++ni) {
                uint32_t b0h = bxh[ni >> 1][(ni & 1) * 2];
                uint32_t b1h = bxh[ni >> 1][(ni & 1) * 2 + 1];
                uint32_t b0l = bxl[ni >> 1][(ni & 1) * 2];
                uint32_t b1l = bxl[ni >> 1][(ni & 1) * 2 + 1];
                mma16816(aL[ni], wh, b0h, b1h);
                mma16816(aL[ni], wh, b0l, b1l);
                mma16816(aL[ni], wl, b0h, b1h);
            }
        }

        // ---- softmax over k (bias, max, exp, sum) ----
        float bb0 = cbs[row0], bb1 = cbs[row1];
        float mq[10];
#pragma unroll
        for (int ni = 0; ni < 5; ++ni) {
            aL[ni][0] += bb0; aL[ni][1] += bb0;
            aL[ni][2] += bb1; aL[ni][3] += bb1;
            mq[ni * 2]     = fmaxf(aL[ni][0], aL[ni][2]);
            mq[ni * 2 + 1] = fmaxf(aL[ni][1], aL[ni][3]);
        }
#pragma unroll
        for (int e = 0; e < 10; ++e) {
            mq[e] = fmaxf(mq[e], __shfl_xor_sync(0xffffffffu, mq[e], 4));
            mq[e] = fmaxf(mq[e], __shfl_xor_sync(0xffffffffu, mq[e], 8));
            mq[e] = fmaxf(mq[e], __shfl_xor_sync(0xffffffffu, mq[e], 16));
        }
        if (L < 4) {
#pragma unroll
            for (int ni = 0; ni < 5; ++ni) {
                int qc = qh * 40 + ni * 8 + L * 2;
                sred[wk * 80 + qc]     = mq[ni * 2];
                sred[wk * 80 + qc + 1] = mq[ni * 2 + 1];
            }
        }
        __syncthreads();
#pragma unroll
        for (int ni = 0; ni < 5; ++ni) {
            int qc = qh * 40 + ni * 8 + (L & 3) * 2;
            float m0 = fmaxf(fmaxf(sred[qc], sred[80 + qc]),
                             fmaxf(sred[160 + qc], sred[240 + qc]));
            float m1 = fmaxf(fmaxf(sred[qc + 1], sred[80 + qc + 1]),
                             fmaxf(sred[160 + qc + 1], sred[240 + qc + 1]));
            aL[ni][0] = __expf(aL[ni][0] - m0);
            aL[ni][2] = __expf(aL[ni][2] - m0);
            aL[ni][1] = __expf(aL[ni][1] - m1);
            aL[ni][3] = __expf(aL[ni][3] - m1);
            mq[ni * 2]     = aL[ni][0] + aL[ni][2];
            mq[ni * 2 + 1] = aL[ni][1] + aL[ni][3];
        }
        __syncthreads();
#pragma unroll
        for (int e = 0; e < 10; ++e) {
            mq[e] += __shfl_xor_sync(0xffffffffu, mq[e], 4);
            mq[e] += __shfl_xor_sync(0xffffffffu, mq[e], 8);
            mq[e] += __shfl_xor_sync(0xffffffffu, mq[e], 16);
        }
        if (L < 4) {
#pragma unroll
            for (int ni = 0; ni < 5; ++ni) {
                int qc = qh * 40 + ni * 8 + L * 2;
                sred[wk * 80 + qc]     = mq[ni * 2];
                sred[wk * 80 + qc + 1] = mq[ni * 2 + 1];
            }
        }
        __syncthreads();
        float s0 = 0.f, s1 = 0.f;   // per-k-row a-sums
#pragma unroll
        for (int ni = 0; ni < 5; ++ni) {
            int qc = qh * 40 + ni * 8 + (L & 3) * 2;
            float d0 = sred[qc] + sred[80 + qc] + sred[160 + qc] + sred[240 + qc];
            float d1 = sred[qc + 1] + sred[80 + qc + 1] + sred[160 + qc + 1] + sred[240 + qc + 1];
            float i0 = 1.0f / d0, i1 = 1.0f / d1;
            aL[ni][0] *= i0; aL[ni][2] *= i0;
            aL[ni][1] *= i1; aL[ni][3] *= i1;
            s0 += aL[ni][0] + aL[ni][1];
            s1 += aL[ni][2] + aL[ni][3];
            // write a to smem [k][q]
            unsigned short hh, ll;
            bsplit(aL[ni][0], hh, ll);
            sAH[row0 * F_RS + qc] = hh; sAL[row0 * F_RS + qc] = ll;
            bsplit(aL[ni][1], hh, ll);
            sAH[row0 * F_RS + qc + 1] = hh; sAL[row0 * F_RS + qc + 1] = ll;
            bsplit(aL[ni][2], hh, ll);
            sAH[row1 * F_RS + qc] = hh; sAL[row1 * F_RS + qc] = ll;
            bsplit(aL[ni][3], hh, ll);
            sAH[row1 * F_RS + qc + 1] = hh; sAL[row1 * F_RS + qc + 1] = ll;
        }
        // a-sums: reduce over q lanes (xor 1,2), accumulate per (qh,k)
        s0 += __shfl_xor_sync(0xffffffffu, s0, 1);
        s0 += __shfl_xor_sync(0xffffffffu, s0, 2);
        s1 += __shfl_xor_sync(0xffffffffu, s1, 1);
        s1 += __shfl_xor_sync(0xffffffffu, s1, 2);
        if ((L & 3) == 0) {
            sCA[qh * 64 + row0] += s0;
            sCA[qh * 64 + row1] += s1;
        }
        __syncthreads();

        // ---- chunk GEMM: D2[k16][c64] per warp, K=q 80 ----
#pragma unroll
        for (int kq = 0; kq < 5; ++kq) {
            uint32_t ah[4], al[4];
            uint32_t offa = (uint32_t)((wk * 16 + a_row) * F_RS + kq * 16 + a_ch) * 2;
            ldm_x4(ah, sb + F_AH + offa);
            ldm_x4(al, sb + F_AL + offa);
            uint32_t bh[4][4], bl[4][4];
#pragma unroll
            for (int nb = 0; nb < 4; ++nb) {
                uint32_t offb = (uint32_t)((wc * 64 + nb * 16 + b_row) * F_RS + kq * 16 + b_ch) * 2;
                ldm_x4(bh[nb], sb + F_XH + offb);
                ldm_x4(bl[nb], sb + F_XL + offb);
            }
#pragma unroll
            for (int ni = 0; ni < 8; ++ni) {
                uint32_t b0h = bh[ni >> 1][(ni & 1) * 2];
                uint32_t b1h = bh[ni >> 1][(ni & 1) * 2 + 1];
                uint32_t b0l = bl[ni >> 1][(ni & 1) * 2];
                uint32_t b1l = bl[ni >> 1][(ni & 1) * 2 + 1];
                mma16816(acc2[ni], ah, b0h, b1h);
                mma16816(acc2[ni], ah, b0l, b1l);
                mma16816(acc2[ni], al, b0h, b1h);
            }
        }
        __syncthreads();
    }

    // chunk a-sums
    if (tid < 64)
        g_ca[((size_t)n * NCH + j) * KC + tid] = sCA[tid] + sCA[64 + tid];

    // direct (k,c) store
    float* ob = g_cwx + (size_t)(n * NCH + j) * KC * CD;
    int k0  = wk * 16 + (L >> 2);
    int cb0 = wc * 64 + (L & 3) * 2;
#pragma unroll
    for (int ni = 0; ni < 8; ++ni) {
        int c = cb0 + ni * 8;
        *(float2*)&ob[(size_t)k0 * CD + c]       = make_float2(acc2[ni][0], acc2[ni][1]);
        *(float2*)&ob[(size_t)(k0 + 8) * CD + c] = make_float2(acc2[ni][2], acc2[ni][3]);
    }
}

// ---------------------------------------------------------------------------
// Kernel C1 (sliding windows): one block per (n,k), 128 threads (c).
// Loads the 90-chunk slice once, slides +3/-3 chunks per window.
// Global norm = 1/8 exact (64 unit sub-vectors).
// ---------------------------------------------------------------------------
__global__ __launch_bounds__(128) void kC1(const float* __restrict__ centers) {
    __shared__ float ch[NCH][CD];
    __shared__ float ca[NCH];
    __shared__ float red[4];

    const int n = blockIdx.x / KC;
    const int k = blockIdx.x % KC;
    const int c = threadIdx.x;
    const int L = c & 31;
    const int w = c >> 5;

    const float* base = g_cwx + (((size_t)n * NCH) * KC + k) * CD + c;
#pragma unroll 6
    for (int jj = 0; jj < NCH; ++jj)
        ch[jj][c] = base[(size_t)jj * KC * CD];
    if (c < NCH) ca[c] = g_ca[((size_t)n * NCH + c) * KC + k];
    const float cen = centers[(size_t)k * CD + c];
    __syncthreads();

    float s = 0.f, As = 0.f;
#pragma unroll
    for (int i = 0; i < 20; ++i) {
        int jj = (i + 80) % NCH;
        s  += ch[jj][c];
        As += ca[jj];
    }

    for (int t = 0; t < NW; ++t) {
        float r  = s - cen * As;
        float ns = r * r;
#pragma unroll
        for (int off = 16; off > 0; off >>= 1)
            ns += __shfl_xor_sync(0xffffffffu, ns, off);
        if (L == 0) red[w] = ns;
        __syncthreads();
        float tot = red[0] + red[1] + red[2] + red[3];
        float inv = 0.125f / fmaxf(sqrtf(tot), 1e-12f);

        unsigned short hh, ll;
        bsplit(r * inv, hh, ll);
        size_t idx = (size_t)(n * NW + t) * KD + (size_t)k * CD + c;
        g_vh[idx] = hh;
        g_vl[idx] = ll;

        if (t < NW - 1) {
#pragma unroll
            for (int d = 0; d < 3; ++d) {
                int ja = (3 * t + 10 + d) % NCH;
                int js = (3 * t + 80 + d) % NCH;
                s  += ch[ja][c] - ch[js][c];
                As += ca[ja] - ca[js];
            }
        }
        __syncthreads();
    }
}

// ---------------------------------------------------------------------------
// Kernel C2 (mma.sync bf16): split-K partials of (256x8192)@(8192x256)
// ---------------------------------------------------------------------------
#define C2_RS  72
#define C2_AH  0
#define C2_AL  18432
#define C2_BH  36864
#define C2_BL  46080
#define C2_SMEM 55296

__global__ __launch_bounds__(256, 2) void kC2() {
    extern __shared__ char smem[];
    const uint32_t sb = smem_u32(smem);
    const int tid = threadIdx.x;
    const int wid = tid >> 5;
    const int L   = tid & 31;
    const int m0  = blockIdx.x * 128;
    const int n0  = blockIdx.y * 64;
    const int k0  = blockIdx.z * 512;

    unsigned short* sAH = (unsigned short*)(smem + C2_AH);
    unsigned short* sAL = (unsigned short*)(smem + C2_AL);
    unsigned short* sBH = (unsigned short*)(smem + C2_BH);
    unsigned short* sBL = (unsigned short*)(smem + C2_BL);

    const int wm = wid & 1;
    const int wn = wid >> 1;

    float acc[4][2][4];
#pragma unroll
    for (int mi = 0; mi < 4; mi++)
#pragma unroll
        for (int ni = 0; ni < 2; ni++)
#pragma unroll
            for (int e = 0; e < 4; e++) acc[mi][ni][e] = 0.f;

    const int a_row = (L & 7) + ((L >> 3) & 1) * 8;
    const int a_ch  = (L >> 4) * 8;
    const int b_row = (L & 7) + (L >> 4) * 8;
    const int b_ch  = ((L >> 3) & 1) * 8;

    for (int stage = 0; stage < 8; ++stage) {
        int kb = k0 + stage * 64;
#pragma unroll
        for (int it = 0; it < 4; ++it) {
            int p = tid + it * 256;
            int row = p >> 3, cg = (p & 7) * 8;
            size_t g = (size_t)(m0 + row) * KD + kb + cg;
            *(uint4*)&sAH[row * C2_RS + cg] = *(const uint4*)&g_vh[g];
            *(uint4*)&sAL[row * C2_RS + cg] = *(const uint4*)&g_vl[g];
        }
#pragma unroll
        for (int it = 0; it < 2; ++it) {
            int p = tid + it * 256;
            int row = p >> 3, cg = (p & 7) * 8;
            size_t g = (size_t)(n0 + row) * KD + kb + cg;
            *(uint4*)&sBH[row * C2_RS + cg] = *(const uint4*)&g_wh[g];
            *(uint4*)&sBL[row * C2_RS + cg] = *(const uint4*)&g_wl[g];
        }
        __syncthreads();

#pragma unroll
        for (int ks = 0; ks < 4; ++ks) {
            int kc = ks * 16;
            uint32_t bhf[4], blf[4];
            {
                uint32_t off = (uint32_t)((wn * 16 + b_row) * C2_RS + kc + b_ch) * 2;
                ldm_x4(bhf, sb + C2_BH + off);
                ldm_x4(blf, sb + C2_BL + off);
            }
#pragma unroll
            for (int mi = 0; mi < 4; mi++) {
                uint32_t ah[4], al[4];
                uint32_t off = (uint32_t)((wm * 64 + mi * 16 + a_row) * C2_RS + kc + a_ch) * 2;
                ldm_x4(ah, sb + C2_AH + off);
                ldm_x4(al, sb + C2_AL + off);
#pragma unroll
                for (int ni = 0; ni < 2; ni++) {
                    mma16816(acc[mi][ni], ah, bhf[ni * 2], bhf[ni * 2 + 1]);
                    mma16816(acc[mi][ni], ah, blf[ni * 2], blf[ni * 2 + 1]);
                    mma16816(acc[mi][ni], al, bhf[ni * 2], bhf[ni * 2 + 1]);
                }
            }
        }
        __syncthreads();
    }

    float* pb = g_part + (size_t)blockIdx.z * NR * OD;
#pragma unroll
    for (int mi = 0; mi < 4; mi++) {
        int m_lo = m0 + wm * 64 + mi * 16 + (L >> 2);
        int nn   = n0 + wn * 16 + (L & 3) * 2;
#pragma unroll
        for (int ni = 0; ni < 2; ni++) {
            int nc = nn + ni * 8;
            if (m_lo < NR)
                *(float2*)&pb[(size_t)m_lo * OD + nc] =
                    make_float2(acc[mi][ni][0], acc[mi][ni][1]);
            if (m_lo + 8 < NR)
                *(float2*)&pb[(size_t)(m_lo + 8) * OD + nc] =
                    make_float2(acc[mi][ni][2], acc[mi][ni][3]);
        }
    }
}

// ---------------------------------------------------------------------------
// Kernel C3: reduce split-K partials + bias + final row L2 norm -> output
// ---------------------------------------------------------------------------
__global__ __launch_bounds__(256) void kC3(const float* __restrict__ mb,
                                           float* __restrict__ out) {
    __shared__ float red[8];
    const int rrow = blockIdx.x;
    const int tid  = threadIdx.x;
    float s = mb[tid];
#pragma unroll
    for (int ks = 0; ks < KSP; ks++)
        s += g_part[((size_t)ks * NR + rrow) * OD + tid];
    float sq = s * s;
#pragma unroll
    for (int off = 16; off > 0; off >>= 1)
        sq += __shfl_xor_sync(0xffffffffu, sq, off);
    if ((tid & 31) == 0) red[tid >> 5] = sq;
    __syncthreads();
    float tot = 0.f;
#pragma unroll
    for (int i = 0; i < 8; i++) tot += red[i];
    out[(size_t)rrow * OD + tid] = s / fmaxf(sqrtf(tot), 1e-12f);
}

extern "C" void kernel_launch(void* const* d_in, const int* in_sizes, int n_in,
                              void* d_out, int out_size) {
    (void)in_sizes; (void)n_in; (void)out_size;
    const float* x       = (const float*)d_in[0];
    const float* centers = (const float*)d_in[1];
    const float* cw      = (const float*)d_in[2];
    const float* cb      = (const float*)d_in[3];
    const float* mw      = (const float*)d_in[4];
    const float* mb      = (const float*)d_in[5];
    float* out = (float*)d_out;

    cudaFuncSetAttribute(kF, cudaFuncAttributeMaxDynamicSharedMemorySize, F_SMEM);
    cudaFuncSetAttribute(kC2, cudaFuncAttributeMaxDynamicSharedMemorySize, C2_SMEM);

    kW<<<OD * KD / (256 * 8), 256>>>(mw);
    kF<<<NB * NCH, 256, F_SMEM>>>(x, cw, cb);
    kC1<<<NB * KC, 128>>>(centers);
    kC2<<<dim3(2, 4, KSP), 256, C2_SMEM>>>();
    kC3<<<NR, 256>>>(mb, out);
}

// round 6
// speedup vs baseline: 1.0263x; 1.0263x over previous
#include <cuda_runtime.h>
#include <cuda_bf16.h>
#include <math.h>
#include <stdint.h>

#define NB 8
#define CD 128
#define KC 64
#define HD 16
#define WD 900
#define HW 14400
#define NCH 90
#define NW 30
#define NR 240
#define NRP 256
#define OD 256
#define KSP 32
#define KD 8192

__device__ unsigned short g_a_hi[(size_t)NB * KC * HW];   // bf16 bits, (n,k,q)
__device__ unsigned short g_a_lo[(size_t)NB * KC * HW];
__device__ float g_cwx[(size_t)NB * NCH * KC * CD];       // (n,j,k,c)
__device__ float g_ca[(size_t)NB * NCH * KC];             // (n,j,k)
__device__ unsigned short g_vh[(size_t)NRP * KD];         // vlad bf16 hi (rows>=240 stay 0)
__device__ unsigned short g_vl[(size_t)NRP * KD];
__device__ unsigned short g_wh[(size_t)OD * KD];
__device__ unsigned short g_wl[(size_t)OD * KD];
__device__ float g_part[(size_t)KSP * NR * OD];

// ---------------------------------------------------------------------------
// helpers
// ---------------------------------------------------------------------------
__device__ __forceinline__ uint32_t smem_u32(const void* p) {
    uint32_t a;
    asm("{ .reg .u64 t; cvta.to.shared.u64 t, %1; cvt.u32.u64 %0, t; }"
        : "=r"(a) : "l"(p));
    return a;
}
__device__ __forceinline__ void ldm_x4(uint32_t (&r)[4], uint32_t addr) {
    asm volatile("ldmatrix.sync.aligned.m8n8.x4.shared.b16 {%0,%1,%2,%3}, [%4];"
                 : "=r"(r[0]), "=r"(r[1]), "=r"(r[2]), "=r"(r[3]) : "r"(addr));
}
__device__ __forceinline__ void mma16816(float (&d)[4], const uint32_t (&a)[4],
                                         const uint32_t b0, const uint32_t b1) {
    asm volatile(
        "mma.sync.aligned.m16n8k16.row.col.f32.bf16.bf16.f32 "
        "{%0,%1,%2,%3}, {%4,%5,%6,%7}, {%8,%9}, {%0,%1,%2,%3};"
        : "+f"(d[0]), "+f"(d[1]), "+f"(d[2]), "+f"(d[3])
        : "r"(a[0]), "r"(a[1]), "r"(a[2]), "r"(a[3]), "r"(b0), "r"(b1));
}
__device__ __forceinline__ void bsplit(float v, unsigned short& h, unsigned short& l) {
    __nv_bfloat16 bh = __float2bfloat16(v);
    __nv_bfloat16 bl = __float2bfloat16(v - __bfloat162float(bh));
    h = __bfloat16_as_ushort(bh);
    l = __bfloat16_as_ushort(bl);
}
__device__ __forceinline__ float bf(unsigned short u) {
    return __bfloat162float(__ushort_as_bfloat16(u));
}
__device__ __forceinline__ void cpa16(uint32_t saddr, const void* g) {
    asm volatile("cp.async.cg.shared.global [%0], [%1], 16;" :: "r"(saddr), "l"(g));
}
#define CPA_COMMIT() asm volatile("cp.async.commit_group;" ::: "memory")
#define CPA_WAIT1()  asm volatile("cp.async.wait_group 1;" ::: "memory")
#define CPA_WAIT0()  asm volatile("cp.async.wait_group 0;" ::: "memory")

// ---------------------------------------------------------------------------
// Kernel W: convert mlp_w to bf16 hi/lo
// ---------------------------------------------------------------------------
__global__ __launch_bounds__(256) void kW(const float* __restrict__ mw) {
    size_t base = ((size_t)blockIdx.x * 256 + threadIdx.x) * 8;
    float4 v0 = *(const float4*)(mw + base);
    float4 v1 = *(const float4*)(mw + base + 4);
    float vv[8] = {v0.x, v0.y, v0.z, v0.w, v1.x, v1.y, v1.z, v1.w};
    unsigned short h[8], l[8];
#pragma unroll
    for (int i = 0; i < 8; i++) bsplit(vv[i], h[i], l[i]);
    *(ushort4*)(g_wh + base)     = make_ushort4(h[0], h[1], h[2], h[3]);
    *(ushort4*)(g_wh + base + 4) = make_ushort4(h[4], h[5], h[6], h[7]);
    *(ushort4*)(g_wl + base)     = make_ushort4(l[0], l[1], l[2], l[3]);
    *(ushort4*)(g_wl + base + 4) = make_ushort4(l[4], l[5], l[6], l[7]);
}

// ---------------------------------------------------------------------------
// Kernel A (mma.sync): logits D[q,k] = sum_c x[c,q] w[k,c]; softmax over k in
// fragments; output a as bf16 hi/lo, layout (n,k,q).
// ---------------------------------------------------------------------------
#define A_RS   136
#define A_XH   0
#define A_XL   (A_XH + 128 * A_RS * 2)   // 34816
#define A_WH   (A_XL + 128 * A_RS * 2)   // 69632
#define A_WL   (A_WH + 64 * A_RS * 2)    // 87040
#define A_CB   (A_WL + 64 * A_RS * 2)    // 104448
#define A_SMEM (A_CB + 256)

__global__ __launch_bounds__(256, 1) void kA(const float* __restrict__ x,
                                             const float* __restrict__ cw,
                                             const float* __restrict__ cb) {
    extern __shared__ char smem[];
    const uint32_t sb = smem_u32(smem);
    unsigned short* sXH = (unsigned short*)(smem + A_XH);
    unsigned short* sXL = (unsigned short*)(smem + A_XL);
    unsigned short* sWH = (unsigned short*)(smem + A_WH);
    unsigned short* sWL = (unsigned short*)(smem + A_WL);
    float* cbs = (float*)(smem + A_CB);

    const int tid = threadIdx.x;
    const int wid = tid >> 5;
    const int L   = tid & 31;
    const int n   = blockIdx.x / 113;
    const int q0  = (blockIdx.x % 113) * 128;
    const int vq  = (HW - q0 < 128) ? (HW - q0) : 128;

    // stage W[k][c] hi/lo
    {
        int k = tid >> 2, cg = (tid & 3) * 32;
        const float* wp = cw + k * CD + cg;
#pragma unroll
        for (int it = 0; it < 8; ++it) {
            float4 v = *(const float4*)(wp + it * 4);
            unsigned short h[4], l[4];
            bsplit(v.x, h[0], l[0]); bsplit(v.y, h[1], l[1]);
            bsplit(v.z, h[2], l[2]); bsplit(v.w, h[3], l[3]);
            *(ushort4*)&sWH[k * A_RS + cg + it * 4] = make_ushort4(h[0], h[1], h[2], h[3]);
            *(ushort4*)&sWL[k * A_RS + cg + it * 4] = make_ushort4(l[0], l[1], l[2], l[3]);
        }
    }
    if (tid < 64) cbs[tid] = cb[tid];

    // stage X^T: sX[q][c] hi/lo
    {
        int c = tid >> 1, qh = (tid & 1) * 64;
        const float* xp = x + (size_t)n * CD * HW + (size_t)c * HW + q0 + qh;
#pragma unroll
        for (int it = 0; it < 16; ++it) {
            int qq = qh + it * 4;
            float4 v = (qq < vq) ? *(const float4*)(xp + it * 4)
                                 : make_float4(0.f, 0.f, 0.f, 0.f);
            float vv[4] = {v.x, v.y, v.z, v.w};
#pragma unroll
            for (int e = 0; e < 4; ++e) {
                unsigned short h, l;
                bsplit(vv[e], h, l);
                sXH[(qq + e) * A_RS + c] = h;
                sXL[(qq + e) * A_RS + c] = l;
            }
        }
    }
    __syncthreads();

    const int a_row = (L & 7) + ((L >> 3) & 1) * 8;
    const int a_ch  = (L >> 4) * 8;
    const int b_row = (L & 7) + (L >> 4) * 8;
    const int b_ch  = ((L >> 3) & 1) * 8;

    float acc[8][4];
#pragma unroll
    for (int ni = 0; ni < 8; ni++)
#pragma unroll
        for (int e = 0; e < 4; e++) acc[ni][e] = 0.f;

#pragma unroll
    for (int kc = 0; kc < 128; kc += 16) {
        uint32_t axh[4], axl[4];
        uint32_t offa = (uint32_t)((wid * 16 + a_row) * A_RS + kc + a_ch) * 2;
        ldm_x4(axh, sb + A_XH + offa);
        ldm_x4(axl, sb + A_XL + offa);
        uint32_t bh[4][4], bl[4][4];
#pragma unroll
        for (int nb = 0; nb < 4; ++nb) {
            uint32_t offb = (uint32_t)((nb * 16 + b_row) * A_RS + kc + b_ch) * 2;
            ldm_x4(bh[nb], sb + A_WH + offb);
            ldm_x4(bl[nb], sb + A_WL + offb);
        }
#pragma unroll
        for (int ni = 0; ni < 8; ++ni) {
            uint32_t b0h = bh[ni >> 1][(ni & 1) * 2];
            uint32_t b1h = bh[ni >> 1][(ni & 1) * 2 + 1];
            uint32_t b0l = bl[ni >> 1][(ni & 1) * 2];
            uint32_t b1l = bl[ni >> 1][(ni & 1) * 2 + 1];
            mma16816(acc[ni], axh, b0h, b1h);
            mma16816(acc[ni], axh, b0l, b1l);
            mma16816(acc[ni], axl, b0h, b1h);
        }
    }

    // bias + softmax over k
    float m0 = -1e30f, m1 = -1e30f;
#pragma unroll
    for (int ni = 0; ni < 8; ++ni) {
        int k0 = ni * 8 + (L & 3) * 2;
        float b0 = cbs[k0], b1 = cbs[k0 + 1];
        acc[ni][0] += b0; acc[ni][1] += b1;
        acc[ni][2] += b0; acc[ni][3] += b1;
        m0 = fmaxf(m0, fmaxf(acc[ni][0], acc[ni][1]));
        m1 = fmaxf(m1, fmaxf(acc[ni][2], acc[ni][3]));
    }
    m0 = fmaxf(m0, __shfl_xor_sync(0xffffffffu, m0, 1));
    m0 = fmaxf(m0, __shfl_xor_sync(0xffffffffu, m0, 2));
    m1 = fmaxf(m1, __shfl_xor_sync(0xffffffffu, m1, 1));
    m1 = fmaxf(m1, __shfl_xor_sync(0xffffffffu, m1, 2));
    float s0 = 0.f, s1 = 0.f;
#pragma unroll
    for (int ni = 0; ni < 8; ++ni) {
        acc[ni][0] = __expf(acc[ni][0] - m0);
        acc[ni][1] = __expf(acc[ni][1] - m0);
        acc[ni][2] = __expf(acc[ni][2] - m1);
        acc[ni][3] = __expf(acc[ni][3] - m1);
        s0 += acc[ni][0] + acc[ni][1];
        s1 += acc[ni][2] + acc[ni][3];
    }
    s0 += __shfl_xor_sync(0xffffffffu, s0, 1);
    s0 += __shfl_xor_sync(0xffffffffu, s0, 2);
    s1 += __shfl_xor_sync(0xffffffffu, s1, 1);
    s1 += __shfl_xor_sync(0xffffffffu, s1, 2);
    float i0 = 1.0f / s0, i1 = 1.0f / s1;

    __syncthreads();   // reuse sXH/sXL as a-tile [k][q]
    unsigned short* sAH = sXH;
    unsigned short* sAL = sXL;
    {
        int qr0 = wid * 16 + (L >> 2);
        int qr1 = qr0 + 8;
#pragma unroll
        for (int ni = 0; ni < 8; ++ni) {
            int k0 = ni * 8 + (L & 3) * 2;
            unsigned short h, l;
            bsplit(acc[ni][0] * i0, h, l);
            sAH[k0 * A_RS + qr0] = h;       sAL[k0 * A_RS + qr0] = l;
            bsplit(acc[ni][1] * i0, h, l);
            sAH[(k0 + 1) * A_RS + qr0] = h; sAL[(k0 + 1) * A_RS + qr0] = l;
            bsplit(acc[ni][2] * i1, h, l);
            sAH[k0 * A_RS + qr1] = h;       sAL[k0 * A_RS + qr1] = l;
            bsplit(acc[ni][3] * i1, h, l);
            sAH[(k0 + 1) * A_RS + qr1] = h; sAL[(k0 + 1) * A_RS + qr1] = l;
        }
    }
    __syncthreads();

#pragma unroll
    for (int it = 0; it < 4; ++it) {
        int e = tid + it * 256;
        int k = e >> 4, qg = (e & 15) * 8;
        if (qg < vq) {
            size_t g = ((size_t)n * KC + k) * HW + q0 + qg;
            *(uint4*)&g_a_hi[g] = *(uint4*)&sAH[k * A_RS + qg];
            *(uint4*)&g_a_lo[g] = *(uint4*)&sAL[k * A_RS + qg];
        }
    }
}

// ---------------------------------------------------------------------------
// Kernel B (mma.sync): per (n,j): D[k,c] = sum_{q in 160} a[k,q] x[c,q]
// ---------------------------------------------------------------------------
#define B_RS   88
#define B_AH   0
#define B_AL   11264
#define B_XH   22528
#define B_XL   45056
#define B_RED  67584
#define B_SMEM (B_RED + 4096)

__global__ __launch_bounds__(256, 2) void kB(const float* __restrict__ x) {
    extern __shared__ char smem[];
    const uint32_t sb = smem_u32(smem);
    unsigned short* sAH = (unsigned short*)(smem + B_AH);
    unsigned short* sAL = (unsigned short*)(smem + B_AL);
    unsigned short* sXH = (unsigned short*)(smem + B_XH);
    unsigned short* sXL = (unsigned short*)(smem + B_XL);
    float* redA = (float*)(smem + B_RED);

    const int tid = threadIdx.x;
    const int wid = tid >> 5;
    const int L   = tid & 31;
    const int n = blockIdx.x / NCH;
    const int j = blockIdx.x % NCH;

    const int wk = wid & 3;
    const int wc = wid >> 2;

    const int a_row = (L & 7) + ((L >> 3) & 1) * 8;
    const int a_ch  = (L >> 4) * 8;
    const int b_row = (L & 7) + (L >> 4) * 8;
    const int b_ch  = ((L >> 3) & 1) * 8;

    float acc[8][4];
#pragma unroll
    for (int ni = 0; ni < 8; ni++)
#pragma unroll
        for (int e = 0; e < 4; e++) acc[ni][e] = 0.f;

#pragma unroll
    for (int s = 0; s < 2; ++s) {
#pragma unroll
        for (int it = 0; it < 2; ++it) {
            int p = tid + it * 256;
            int k = p >> 3, h8 = p & 7;
            int h = s * 8 + h8;
            size_t gidx = ((size_t)n * KC + k) * HW + (size_t)h * WD + (size_t)j * 10;
            const uint* gh = (const uint*)(g_a_hi + gidx);
            const uint* gl = (const uint*)(g_a_lo + gidx);
            int colb = k * B_RS + h8 * 10;
            float sum = 0.f;
#pragma unroll
            for (int w2 = 0; w2 < 5; ++w2) {
                uint vh = gh[w2], vl = gl[w2];
                *(uint*)&sAH[colb + w2 * 2] = vh;
                *(uint*)&sAL[colb + w2 * 2] = vl;
                sum += bf((unsigned short)(vh & 0xffff)) + bf((unsigned short)(vh >> 16)) +
                       bf((unsigned short)(vl & 0xffff)) + bf((unsigned short)(vl >> 16));
            }
            redA[h * 64 + k] = sum;
        }
#pragma unroll
        for (int it = 0; it < 4; ++it) {
            int p = tid + it * 256;
            int c = p >> 3, h8 = p & 7;
            int h = s * 8 + h8;
            const float* gp = x + (size_t)n * CD * HW + (size_t)c * HW +
                              (size_t)h * WD + (size_t)j * 10;
            int colb = c * B_RS + h8 * 10;
#pragma unroll
            for (int w2 = 0; w2 < 5; ++w2) {
                float2 v = *(const float2*)(gp + w2 * 2);
                unsigned short h0, l0, h1, l1;
                bsplit(v.x, h0, l0);
                bsplit(v.y, h1, l1);
                *(uint*)&sXH[colb + w2 * 2] = (uint)h0 | ((uint)h1 << 16);
                *(uint*)&sXL[colb + w2 * 2] = (uint)l0 | ((uint)l1 << 16);
            }
        }
        __syncthreads();

#pragma unroll
        for (int ks = 0; ks < 5; ++ks) {
            int kc = ks * 16;
            uint32_t ah[4], al[4];
            uint32_t offa = (uint32_t)((wk * 16 + a_row) * B_RS + kc + a_ch) * 2;
            ldm_x4(ah, sb + B_AH + offa);
            ldm_x4(al, sb + B_AL + offa);
            uint32_t bh[4][4], bl[4][4];
#pragma unroll
            for (int nb = 0; nb < 4; ++nb) {
                uint32_t offb = (uint32_t)((wc * 64 + nb * 16 + b_row) * B_RS + kc + b_ch) * 2;
                ldm_x4(bh[nb], sb + B_XH + offb);
                ldm_x4(bl[nb], sb + B_XL + offb);
            }
#pragma unroll
            for (int ni = 0; ni < 8; ++ni) {
                uint32_t b0h = bh[ni >> 1][(ni & 1) * 2];
                uint32_t b1h = bh[ni >> 1][(ni & 1) * 2 + 1];
                uint32_t b0l = bl[ni >> 1][(ni & 1) * 2];
                uint32_t b1l = bl[ni >> 1][(ni & 1) * 2 + 1];
                mma16816(acc[ni], ah, b0h, b1h);
                mma16816(acc[ni], ah, b0l, b1l);
                mma16816(acc[ni], al, b0h, b1h);
            }
        }
        __syncthreads();
    }

    if (tid < 64) {
        float sum = 0.f;
#pragma unroll
        for (int h = 0; h < 16; ++h) sum += redA[h * 64 + tid];
        g_ca[((size_t)n * NCH + j) * KC + tid] = sum;
    }

    float* ob = g_cwx + (size_t)(n * NCH + j) * KC * CD;
    int k0 = wk * 16 + (L >> 2);
    int cb0 = wc * 64 + (L & 3) * 2;
#pragma unroll
    for (int ni = 0; ni < 8; ++ni) {
        int c = cb0 + ni * 8;
        *(float2*)&ob[(size_t)k0 * CD + c]       = make_float2(acc[ni][0], acc[ni][1]);
        *(float2*)&ob[(size_t)(k0 + 8) * CD + c] = make_float2(acc[ni][2], acc[ni][3]);
    }
}

// ---------------------------------------------------------------------------
// Kernel C1 (sliding windows): one block per (n,k), 128 threads (c).
// ---------------------------------------------------------------------------
__global__ __launch_bounds__(128) void kC1(const float* __restrict__ centers) {
    __shared__ float ch[NCH][CD];
    __shared__ float ca[NCH];
    __shared__ float red[4];

    const int n = blockIdx.x / KC;
    const int k = blockIdx.x % KC;
    const int c = threadIdx.x;
    const int L = c & 31;
    const int w = c >> 5;

    const float* base = g_cwx + (((size_t)n * NCH) * KC + k) * CD + c;
#pragma unroll 6
    for (int jj = 0; jj < NCH; ++jj)
        ch[jj][c] = base[(size_t)jj * KC * CD];
    if (c < NCH) ca[c] = g_ca[((size_t)n * NCH + c) * KC + k];
    const float cen = centers[(size_t)k * CD + c];
    __syncthreads();

    float s = 0.f, As = 0.f;
#pragma unroll
    for (int i = 0; i < 20; ++i) {
        int jj = (i + 80) % NCH;
        s  += ch[jj][c];
        As += ca[jj];
    }

    for (int t = 0; t < NW; ++t) {
        float r  = s - cen * As;
        float ns = r * r;
#pragma unroll
        for (int off = 16; off > 0; off >>= 1)
            ns += __shfl_xor_sync(0xffffffffu, ns, off);
        if (L == 0) red[w] = ns;
        __syncthreads();
        float tot = red[0] + red[1] + red[2] + red[3];
        float inv = 0.125f / fmaxf(sqrtf(tot), 1e-12f);

        unsigned short hh, ll;
        bsplit(r * inv, hh, ll);
        size_t idx = (size_t)(n * NW + t) * KD + (size_t)k * CD + c;
        g_vh[idx] = hh;
        g_vl[idx] = ll;

        if (t < NW - 1) {
#pragma unroll
            for (int d = 0; d < 3; ++d) {
                int ja = (3 * t + 10 + d) % NCH;
                int js = (3 * t + 80 + d) % NCH;
                s  += ch[ja][c] - ch[js][c];
                As += ca[ja] - ca[js];
            }
        }
        __syncthreads();
    }
}

// ---------------------------------------------------------------------------
// Kernel C2 (mma.sync bf16, cp.async double-buffered): split-K partials of
// (256x8192)@(8192x256). BM=128, BN=64, K-chunk 256 (4 stages of 64),
// grid (2,4,32).
// ---------------------------------------------------------------------------
#define C2_RS   72
#define C2_AH   0
#define C2_AL   18432
#define C2_BH   36864
#define C2_BL   46080
#define C2_BUF  55296
#define C2_SMEM (C2_BUF * 2)

__device__ __forceinline__ void c2_stage(uint32_t sbuf, int m0, int n0, int kb,
                                         int tid) {
#pragma unroll
    for (int it = 0; it < 4; ++it) {
        int p = tid + it * 256;
        int row = p >> 3, cg = (p & 7) * 8;
        size_t g = (size_t)(m0 + row) * KD + kb + cg;
        cpa16(sbuf + C2_AH + (row * C2_RS + cg) * 2, &g_vh[g]);
        cpa16(sbuf + C2_AL + (row * C2_RS + cg) * 2, &g_vl[g]);
    }
#pragma unroll
    for (int it = 0; it < 2; ++it) {
        int p = tid + it * 256;
        int row = p >> 3, cg = (p & 7) * 8;
        size_t g = (size_t)(n0 + row) * KD + kb + cg;
        cpa16(sbuf + C2_BH + (row * C2_RS + cg) * 2, &g_wh[g]);
        cpa16(sbuf + C2_BL + (row * C2_RS + cg) * 2, &g_wl[g]);
    }
}

__global__ __launch_bounds__(256, 1) void kC2() {
    extern __shared__ char smem[];
    const uint32_t sb = smem_u32(smem);
    const int tid = threadIdx.x;
    const int wid = tid >> 5;
    const int L   = tid & 31;
    const int m0  = blockIdx.x * 128;
    const int n0  = blockIdx.y * 64;
    const int k0  = blockIdx.z * 256;

    const int wm = wid & 1;
    const int wn = wid >> 1;

    float acc[4][2][4];
#pragma unroll
    for (int mi = 0; mi < 4; mi++)
#pragma unroll
        for (int ni = 0; ni < 2; ni++)
#pragma unroll
            for (int e = 0; e < 4; e++) acc[mi][ni][e] = 0.f;

    const int a_row = (L & 7) + ((L >> 3) & 1) * 8;
    const int a_ch  = (L >> 4) * 8;
    const int b_row = (L & 7) + (L >> 4) * 8;
    const int b_ch  = ((L >> 3) & 1) * 8;

    c2_stage(sb, m0, n0, k0, tid);
    CPA_COMMIT();

#pragma unroll
    for (int stage = 0; stage < 4; ++stage) {
        if (stage < 3) {
            c2_stage(sb + ((stage + 1) & 1) * C2_BUF, m0, n0, k0 + (stage + 1) * 64, tid);
            CPA_COMMIT();
            CPA_WAIT1();
        } else {
            CPA_WAIT0();
        }
        __syncthreads();
        uint32_t bufb = sb + (stage & 1) * C2_BUF;

#pragma unroll
        for (int ks = 0; ks < 4; ++ks) {
            int kc = ks * 16;
            uint32_t bhf[4], blf[4];
            {
                uint32_t off = (uint32_t)((wn * 16 + b_row) * C2_RS + kc + b_ch) * 2;
                ldm_x4(bhf, bufb + C2_BH + off);
                ldm_x4(blf, bufb + C2_BL + off);
            }
#pragma unroll
            for (int mi = 0; mi < 4; mi++) {
                uint32_t ah[4], al[4];
                uint32_t off = (uint32_t)((wm * 64 + mi * 16 + a_row) * C2_RS + kc + a_ch) * 2;
                ldm_x4(ah, bufb + C2_AH + off);
                ldm_x4(al, bufb + C2_AL + off);
#pragma unroll
                for (int ni = 0; ni < 2; ni++) {
                    mma16816(acc[mi][ni], ah, bhf[ni * 2], bhf[ni * 2 + 1]);
                    mma16816(acc[mi][ni], ah, blf[ni * 2], blf[ni * 2 + 1]);
                    mma16816(acc[mi][ni], al, bhf[ni * 2], bhf[ni * 2 + 1]);
                }
            }
        }
        __syncthreads();
    }

    float* pb = g_part + (size_t)blockIdx.z * NR * OD;
#pragma unroll
    for (int mi = 0; mi < 4; mi++) {
        int m_lo = m0 + wm * 64 + mi * 16 + (L >> 2);
        int nn   = n0 + wn * 16 + (L & 3) * 2;
#pragma unroll
        for (int ni = 0; ni < 2; ni++) {
            int nc = nn + ni * 8;
            if (m_lo < NR)
                *(float2*)&pb[(size_t)m_lo * OD + nc] =
                    make_float2(acc[mi][ni][0], acc[mi][ni][1]);
            if (m_lo + 8 < NR)
                *(float2*)&pb[(size_t)(m_lo + 8) * OD + nc] =
                    make_float2(acc[mi][ni][2], acc[mi][ni][3]);
        }
    }
}

// ---------------------------------------------------------------------------
// Kernel C3: reduce split-K partials + bias + final row L2 norm -> output
// ---------------------------------------------------------------------------
__global__ __launch_bounds__(256) void kC3(const float* __restrict__ mb,
                                           float* __restrict__ out) {
    __shared__ float red[8];
    const int rrow = blockIdx.x;
    const int tid  = threadIdx.x;
    float s = mb[tid];
#pragma unroll
    for (int ks = 0; ks < KSP; ks++)
        s += g_part[((size_t)ks * NR + rrow) * OD + tid];
    float sq = s * s;
#pragma unroll
    for (int off = 16; off > 0; off >>= 1)
        sq += __shfl_xor_sync(0xffffffffu, sq, off);
    if ((tid & 31) == 0) red[tid >> 5] = sq;
    __syncthreads();
    float tot = 0.f;
#pragma unroll
    for (int i = 0; i < 8; i++) tot += red[i];
    out[(size_t)rrow * OD + tid] = s / fmaxf(sqrtf(tot), 1e-12f);
}

extern "C" void kernel_launch(void* const* d_in, const int* in_sizes, int n_in,
                              void* d_out, int out_size) {
    (void)in_sizes; (void)n_in; (void)out_size;
    const float* x       = (const float*)d_in[0];
    const float* centers = (const float*)d_in[1];
    const float* cw      = (const float*)d_in[2];
    const float* cb      = (const float*)d_in[3];
    const float* mw      = (const float*)d_in[4];
    const float* mb      = (const float*)d_in[5];
    float* out = (float*)d_out;

    cudaFuncSetAttribute(kA, cudaFuncAttributeMaxDynamicSharedMemorySize, A_SMEM);
    cudaFuncSetAttribute(kB, cudaFuncAttributeMaxDynamicSharedMemorySize, B_SMEM);
    cudaFuncSetAttribute(kC2, cudaFuncAttributeMaxDynamicSharedMemorySize, C2_SMEM);

    kW<<<OD * KD / (256 * 8), 256>>>(mw);
    kA<<<NB * 113, 256, A_SMEM>>>(x, cw, cb);
    kB<<<NB * NCH, 256, B_SMEM>>>(x);
    kC1<<<NB * KC, 128>>>(centers);
    kC2<<<dim3(2, 4, KSP), 256, C2_SMEM>>>();
    kC3<<<NR, 256>>>(mb, out);
}

// round 7
// speedup vs baseline: 1.3476x; 1.3131x over previous
#include <cuda_runtime.h>
#include <cuda_bf16.h>
#include <math.h>
#include <stdint.h>

#define NB 8
#define CD 128
#define KC 64
#define HD 16
#define WD 900
#define HW 14400
#define NCH 90
#define NW 30
#define NR 240
#define NRP 256
#define OD 256
#define KSP 32
#define KD 8192

__device__ float g_cwx[(size_t)NB * NCH * KC * CD];       // (n,j,k,c)
__device__ float g_ca[(size_t)NB * NCH * KC];             // (n,j,k)
__device__ unsigned short g_vh[(size_t)NRP * KD];         // vlad bf16 hi (rows>=240 stay 0)
__device__ unsigned short g_vl[(size_t)NRP * KD];
__device__ unsigned short g_wh[(size_t)OD * KD];
__device__ unsigned short g_wl[(size_t)OD * KD];
__device__ float g_part[(size_t)KSP * NR * OD];

// ---------------------------------------------------------------------------
// helpers
// ---------------------------------------------------------------------------
__device__ __forceinline__ uint32_t smem_u32(const void* p) {
    uint32_t a;
    asm("{ .reg .u64 t; cvta.to.shared.u64 t, %1; cvt.u32.u64 %0, t; }"
        : "=r"(a) : "l"(p));
    return a;
}
__device__ __forceinline__ void ldm_x4(uint32_t (&r)[4], uint32_t addr) {
    asm volatile("ldmatrix.sync.aligned.m8n8.x4.shared.b16 {%0,%1,%2,%3}, [%4];"
                 : "=r"(r[0]), "=r"(r[1]), "=r"(r[2]), "=r"(r[3]) : "r"(addr));
}
__device__ __forceinline__ void ldm_x4t(uint32_t (&r)[4], uint32_t addr) {
    asm volatile("ldmatrix.sync.aligned.m8n8.x4.trans.shared.b16 {%0,%1,%2,%3}, [%4];"
                 : "=r"(r[0]), "=r"(r[1]), "=r"(r[2]), "=r"(r[3]) : "r"(addr));
}
__device__ __forceinline__ void mma16816(float (&d)[4], const uint32_t (&a)[4],
                                         const uint32_t b0, const uint32_t b1) {
    asm volatile(
        "mma.sync.aligned.m16n8k16.row.col.f32.bf16.bf16.f32 "
        "{%0,%1,%2,%3}, {%4,%5,%6,%7}, {%8,%9}, {%0,%1,%2,%3};"
        : "+f"(d[0]), "+f"(d[1]), "+f"(d[2]), "+f"(d[3])
        : "r"(a[0]), "r"(a[1]), "r"(a[2]), "r"(a[3]), "r"(b0), "r"(b1));
}
__device__ __forceinline__ void bsplit(float v, unsigned short& h, unsigned short& l) {
    __nv_bfloat16 bh = __float2bfloat16(v);
    __nv_bfloat16 bl = __float2bfloat16(v - __bfloat162float(bh));
    h = __bfloat16_as_ushort(bh);
    l = __bfloat16_as_ushort(bl);
}
__device__ __forceinline__ void cpa16(uint32_t saddr, const void* g) {
    asm volatile("cp.async.cg.shared.global [%0], [%1], 16;" :: "r"(saddr), "l"(g));
}
#define CPA_COMMIT() asm volatile("cp.async.commit_group;" ::: "memory")
#define CPA_WAIT1()  asm volatile("cp.async.wait_group 1;" ::: "memory")
#define CPA_WAIT0()  asm volatile("cp.async.wait_group 0;" ::: "memory")

// ---------------------------------------------------------------------------
// Kernel W: convert mlp_w to bf16 hi/lo
// ---------------------------------------------------------------------------
__global__ __launch_bounds__(256) void kW(const float* __restrict__ mw) {
    size_t base = ((size_t)blockIdx.x * 256 + threadIdx.x) * 8;
    float4 v0 = *(const float4*)(mw + base);
    float4 v1 = *(const float4*)(mw + base + 4);
    float vv[8] = {v0.x, v0.y, v0.z, v0.w, v1.x, v1.y, v1.z, v1.w};
    unsigned short h[8], l[8];
#pragma unroll
    for (int i = 0; i < 8; i++) bsplit(vv[i], h[i], l[i]);
    *(ushort4*)(g_wh + base)     = make_ushort4(h[0], h[1], h[2], h[3]);
    *(ushort4*)(g_wh + base + 4) = make_ushort4(h[4], h[5], h[6], h[7]);
    *(ushort4*)(g_wl + base)     = make_ushort4(l[0], l[1], l[2], l[3]);
    *(ushort4*)(g_wl + base + 4) = make_ushort4(l[4], l[5], l[6], l[7]);
}

// ---------------------------------------------------------------------------
// Kernel F: fused assignment + chunk GEMM, one block (320 thr) per (n,j).
// Phase 1: stage x[c][q160] + W[k][c] hi/lo.
// Phase 2: logits per warp = full k64 (M) x q16 (N), K=c128; softmax over k
//          is warp-local (m-frags + shfl_xor 4/8/16); a -> smem [k][q];
//          a-sums via smem atomics.
// Phase 3: chunk GEMM D[k64,c128] = a @ x^T (8 warps), direct (k,c) store.
// Only 2 __syncthreads.
// ---------------------------------------------------------------------------
#define F_RS   168
#define F_WRS  136
#define F_WH   0
#define F_WL   17408
#define F_XH   34816
#define F_XL   77824
#define F_AH   120832
#define F_AL   142336
#define F_CB   163840
#define F_CA   164096
#define F_SMEM 164352

__global__ __launch_bounds__(320, 1) void kF(const float* __restrict__ x,
                                             const float* __restrict__ cw,
                                             const float* __restrict__ cb) {
    extern __shared__ char smem[];
    const uint32_t sb = smem_u32(smem);
    unsigned short* sWH = (unsigned short*)(smem + F_WH);
    unsigned short* sWL = (unsigned short*)(smem + F_WL);
    unsigned short* sXH = (unsigned short*)(smem + F_XH);
    unsigned short* sXL = (unsigned short*)(smem + F_XL);
    unsigned short* sAH = (unsigned short*)(smem + F_AH);
    unsigned short* sAL = (unsigned short*)(smem + F_AL);
    float* cbs = (float*)(smem + F_CB);
    float* sCA = (float*)(smem + F_CA);

    const int tid = threadIdx.x;
    const int wid = tid >> 5;
    const int L   = tid & 31;
    const int n = blockIdx.x / NCH;
    const int j = blockIdx.x % NCH;

    const int a_row = (L & 7) + ((L >> 3) & 1) * 8;
    const int a_ch  = (L >> 4) * 8;
    const int b_row = (L & 7) + (L >> 4) * 8;
    const int b_ch  = ((L >> 3) & 1) * 8;

    // ---- Phase 1: staging ----
    if (tid < 256) {
        int k = tid >> 2, cg = (tid & 3) * 32;
        const float* wp = cw + k * CD + cg;
#pragma unroll
        for (int it = 0; it < 8; ++it) {
            float4 v = *(const float4*)(wp + it * 4);
            unsigned short h[4], l[4];
            bsplit(v.x, h[0], l[0]); bsplit(v.y, h[1], l[1]);
            bsplit(v.z, h[2], l[2]); bsplit(v.w, h[3], l[3]);
            *(ushort4*)&sWH[k * F_WRS + cg + it * 4] = make_ushort4(h[0], h[1], h[2], h[3]);
            *(ushort4*)&sWL[k * F_WRS + cg + it * 4] = make_ushort4(l[0], l[1], l[2], l[3]);
        }
    }
    if (tid < 64) cbs[tid] = cb[tid];
    if (tid >= 64 && tid < 128) sCA[tid - 64] = 0.f;

#pragma unroll
    for (int it = 0; it < 7; ++it) {
        int p = tid + it * 320;
        if (p < 2048) {
            int c = p >> 4, h = p & 15;
            const float* gp = x + (size_t)n * CD * HW + (size_t)c * HW +
                              (size_t)h * WD + (size_t)j * 10;
            int colb = c * F_RS + h * 10;
#pragma unroll
            for (int w2 = 0; w2 < 5; ++w2) {
                float2 v = *(const float2*)(gp + w2 * 2);
                unsigned short h0, l0, h1, l1;
                bsplit(v.x, h0, l0);
                bsplit(v.y, h1, l1);
                *(uint*)&sXH[colb + w2 * 2] = (uint)h0 | ((uint)h1 << 16);
                *(uint*)&sXL[colb + w2 * 2] = (uint)l0 | ((uint)l1 << 16);
            }
        }
    }
    __syncthreads();

    // ---- Phase 2: logits mma, warp = k64 x q16 (qt = wid*16) ----
    const int qt = wid * 16;
    float lg[4][2][4];
#pragma unroll
    for (int mi = 0; mi < 4; mi++)
#pragma unroll
        for (int ni = 0; ni < 2; ni++)
#pragma unroll
            for (int e = 0; e < 4; e++) lg[mi][ni][e] = 0.f;

#pragma unroll
    for (int kc = 0; kc < 8; ++kc) {
        uint32_t bxh[4], bxl[4];
        uint32_t offx = (uint32_t)((kc * 16 + a_row) * F_RS + qt + a_ch) * 2;
        ldm_x4t(bxh, sb + F_XH + offx);
        ldm_x4t(bxl, sb + F_XL + offx);
#pragma unroll
        for (int mi = 0; mi < 4; ++mi) {
            uint32_t wh[4], wl[4];
            uint32_t offw = (uint32_t)((mi * 16 + a_row) * F_WRS + kc * 16 + a_ch) * 2;
            ldm_x4(wh, sb + F_WH + offw);
            ldm_x4(wl, sb + F_WL + offw);
#pragma unroll
            for (int ni = 0; ni < 2; ++ni) {
                uint32_t b0h = bxh[ni * 2], b1h = bxh[ni * 2 + 1];
                uint32_t b0l = bxl[ni * 2], b1l = bxl[ni * 2 + 1];
                mma16816(lg[mi][ni], wh, b0h, b1h);
                mma16816(lg[mi][ni], wh, b0l, b1l);
                mma16816(lg[mi][ni], wl, b0h, b1h);
            }
        }
    }

    // bias (k = mi*16 + (L>>2) + (e>>1)*8)
    const int r0 = L >> 2;
#pragma unroll
    for (int mi = 0; mi < 4; ++mi) {
        float b0 = cbs[mi * 16 + r0];
        float b1 = cbs[mi * 16 + r0 + 8];
#pragma unroll
        for (int ni = 0; ni < 2; ++ni) {
            lg[mi][ni][0] += b0; lg[mi][ni][1] += b0;
            lg[mi][ni][2] += b1; lg[mi][ni][3] += b1;
        }
    }

    // softmax over k: in-register over (mi, e>>1) then lanes (xor 4,8,16)
    float mx[4];   // index = ni*2 + h, h = e&1
#pragma unroll
    for (int ni = 0; ni < 2; ++ni)
#pragma unroll
        for (int h = 0; h < 2; ++h) {
            float m = -1e30f;
#pragma unroll
            for (int mi = 0; mi < 4; ++mi)
                m = fmaxf(m, fmaxf(lg[mi][ni][h], lg[mi][ni][2 + h]));
            mx[ni * 2 + h] = m;
        }
#pragma unroll
    for (int e = 0; e < 4; ++e) {
        mx[e] = fmaxf(mx[e], __shfl_xor_sync(0xffffffffu, mx[e], 4));
        mx[e] = fmaxf(mx[e], __shfl_xor_sync(0xffffffffu, mx[e], 8));
        mx[e] = fmaxf(mx[e], __shfl_xor_sync(0xffffffffu, mx[e], 16));
    }
    float sm[4] = {0.f, 0.f, 0.f, 0.f};
#pragma unroll
    for (int mi = 0; mi < 4; ++mi)
#pragma unroll
        for (int ni = 0; ni < 2; ++ni)
#pragma unroll
            for (int e = 0; e < 4; ++e) {
                lg[mi][ni][e] = __expf(lg[mi][ni][e] - mx[ni * 2 + (e & 1)]);
                sm[ni * 2 + (e & 1)] += lg[mi][ni][e];
            }
#pragma unroll
    for (int e = 0; e < 4; ++e) {
        sm[e] += __shfl_xor_sync(0xffffffffu, sm[e], 4);
        sm[e] += __shfl_xor_sync(0xffffffffu, sm[e], 8);
        sm[e] += __shfl_xor_sync(0xffffffffu, sm[e], 16);
        sm[e] = 1.0f / sm[e];
    }
#pragma unroll
    for (int mi = 0; mi < 4; ++mi)
#pragma unroll
        for (int ni = 0; ni < 2; ++ni)
#pragma unroll
            for (int e = 0; e < 4; ++e)
                lg[mi][ni][e] *= sm[ni * 2 + (e & 1)];

    // a-sums (per k row over this warp's 16 q) -> smem atomics
#pragma unroll
    for (int mi = 0; mi < 4; ++mi)
#pragma unroll
        for (int rh = 0; rh < 2; ++rh) {
            float rs = lg[mi][0][rh * 2] + lg[mi][0][rh * 2 + 1] +
                       lg[mi][1][rh * 2] + lg[mi][1][rh * 2 + 1];
            rs += __shfl_xor_sync(0xffffffffu, rs, 1);
            rs += __shfl_xor_sync(0xffffffffu, rs, 2);
            if ((L & 3) == 0)
                atomicAdd(&sCA[mi * 16 + r0 + rh * 8], rs);
        }

    // write a -> smem [k][q] hi/lo
    {
        int qb = qt + (L & 3) * 2;
#pragma unroll
        for (int mi = 0; mi < 4; ++mi)
#pragma unroll
            for (int ni = 0; ni < 2; ++ni)
#pragma unroll
                for (int e = 0; e < 4; ++e) {
                    int k = mi * 16 + r0 + (e >> 1) * 8;
                    int q = qb + ni * 8 + (e & 1);
                    unsigned short hh, ll;
                    bsplit(lg[mi][ni][e], hh, ll);
                    sAH[k * F_RS + q] = hh;
                    sAL[k * F_RS + q] = ll;
                }
    }
    __syncthreads();

    if (tid < 64)
        g_ca[((size_t)n * NCH + j) * KC + tid] = sCA[tid];

    // ---- Phase 3: chunk GEMM (8 warps): D[k,c] = a @ x^T, K=q160 ----
    if (wid < 8) {
        const int wk = wid & 3;
        const int wc = wid >> 2;
        float acc[8][4];
#pragma unroll
        for (int ni = 0; ni < 8; ni++)
#pragma unroll
            for (int e = 0; e < 4; e++) acc[ni][e] = 0.f;

#pragma unroll
        for (int kq = 0; kq < 10; ++kq) {
            int kc = kq * 16;
            uint32_t ah[4], al[4];
            uint32_t offa = (uint32_t)((wk * 16 + a_row) * F_RS + kc + a_ch) * 2;
            ldm_x4(ah, sb + F_AH + offa);
            ldm_x4(al, sb + F_AL + offa);
            uint32_t bh[4][4], bl[4][4];
#pragma unroll
            for (int nb = 0; nb < 4; ++nb) {
                uint32_t offb = (uint32_t)((wc * 64 + nb * 16 + b_row) * F_RS + kc + b_ch) * 2;
                ldm_x4(bh[nb], sb + F_XH + offb);
                ldm_x4(bl[nb], sb + F_XL + offb);
            }
#pragma unroll
            for (int ni = 0; ni < 8; ++ni) {
                uint32_t b0h = bh[ni >> 1][(ni & 1) * 2];
                uint32_t b1h = bh[ni >> 1][(ni & 1) * 2 + 1];
                uint32_t b0l = bl[ni >> 1][(ni & 1) * 2];
                uint32_t b1l = bl[ni >> 1][(ni & 1) * 2 + 1];
                mma16816(acc[ni], ah, b0h, b1h);
                mma16816(acc[ni], ah, b0l, b1l);
                mma16816(acc[ni], al, b0h, b1h);
            }
        }

        float* ob = g_cwx + (size_t)(n * NCH + j) * KC * CD;
        int k0  = wk * 16 + (L >> 2);
        int cb0 = wc * 64 + (L & 3) * 2;
#pragma unroll
        for (int ni = 0; ni < 8; ++ni) {
            int c = cb0 + ni * 8;
            *(float2*)&ob[(size_t)k0 * CD + c]       = make_float2(acc[ni][0], acc[ni][1]);
            *(float2*)&ob[(size_t)(k0 + 8) * CD + c] = make_float2(acc[ni][2], acc[ni][3]);
        }
    }
}

// ---------------------------------------------------------------------------
// Kernel C1: warp per (n,k,half); sliding-window sums in registers, chunk
// reads from L2; no smem, no syncthreads. Global norm = 1/8 exact.
// ---------------------------------------------------------------------------
__global__ __launch_bounds__(256) void kC1(const float* __restrict__ centers) {
    const int wi   = blockIdx.x * 8 + (threadIdx.x >> 5);
    const int L    = threadIdx.x & 31;
    const int half = wi & 1;
    const int k    = (wi >> 1) & 63;
    const int n    = wi >> 7;
    const int c4   = L * 4;

    const float* cwb = g_cwx + ((size_t)n * NCH * KC + k) * CD + c4;
    const float* cab = g_ca + (size_t)n * NCH * KC + k;
    const size_t cstep = (size_t)KC * CD;

    const int t0 = half * 15;
    float s0 = 0.f, s1 = 0.f, s2 = 0.f, s3 = 0.f, As = 0.f;
#pragma unroll
    for (int i = 0; i < 20; ++i) {
        int jj = 3 * t0 + i + 80;
        if (jj >= NCH) jj -= NCH;
        float4 v = *(const float4*)(cwb + (size_t)jj * cstep);
        s0 += v.x; s1 += v.y; s2 += v.z; s3 += v.w;
        As += cab[(size_t)jj * KC];
    }
    const float4 cen = *(const float4*)&centers[(size_t)k * CD + c4];

    for (int t = t0; t < t0 + 15; ++t) {
        float r0 = s0 - cen.x * As;
        float r1 = s1 - cen.y * As;
        float r2 = s2 - cen.z * As;
        float r3 = s3 - cen.w * As;
        float ns = r0 * r0 + r1 * r1 + r2 * r2 + r3 * r3;
#pragma unroll
        for (int off = 16; off > 0; off >>= 1)
            ns += __shfl_xor_sync(0xffffffffu, ns, off);
        float inv = 0.125f / fmaxf(sqrtf(ns), 1e-12f);

        unsigned short h[4], l[4];
        bsplit(r0 * inv, h[0], l[0]);
        bsplit(r1 * inv, h[1], l[1]);
        bsplit(r2 * inv, h[2], l[2]);
        bsplit(r3 * inv, h[3], l[3]);
        size_t idx = (size_t)(n * NW + t) * KD + (size_t)k * CD + c4;
        *(ushort4*)&g_vh[idx] = make_ushort4(h[0], h[1], h[2], h[3]);
        *(ushort4*)&g_vl[idx] = make_ushort4(l[0], l[1], l[2], l[3]);

        if (t < t0 + 14) {
#pragma unroll
            for (int d = 0; d < 3; ++d) {
                int ja = 3 * t + 10 + d;
                if (ja >= NCH) ja -= NCH;
                int js = 3 * t + 80 + d;
                if (js >= NCH) js -= NCH;
                float4 va = *(const float4*)(cwb + (size_t)ja * cstep);
                float4 vs = *(const float4*)(cwb + (size_t)js * cstep);
                s0 += va.x - vs.x; s1 += va.y - vs.y;
                s2 += va.z - vs.z; s3 += va.w - vs.w;
                As += cab[(size_t)ja * KC] - cab[(size_t)js * KC];
            }
        }
    }
}

// ---------------------------------------------------------------------------
// Kernel C2 (mma.sync bf16, cp.async double-buffered): split-K partials of
// (256x8192)@(8192x256). BM=128, BN=64, K-chunk 256, grid (2,4,32).
// ---------------------------------------------------------------------------
#define C2_RS   72
#define C2_AH   0
#define C2_AL   18432
#define C2_BH   36864
#define C2_BL   46080
#define C2_BUF  55296
#define C2_SMEM (C2_BUF * 2)

__device__ __forceinline__ void c2_stage(uint32_t sbuf, int m0, int n0, int kb,
                                         int tid) {
#pragma unroll
    for (int it = 0; it < 4; ++it) {
        int p = tid + it * 256;
        int row = p >> 3, cg = (p & 7) * 8;
        size_t g = (size_t)(m0 + row) * KD + kb + cg;
        cpa16(sbuf + C2_AH + (row * C2_RS + cg) * 2, &g_vh[g]);
        cpa16(sbuf + C2_AL + (row * C2_RS + cg) * 2, &g_vl[g]);
    }
#pragma unroll
    for (int it = 0; it < 2; ++it) {
        int p = tid + it * 256;
        int row = p >> 3, cg = (p & 7) * 8;
        size_t g = (size_t)(n0 + row) * KD + kb + cg;
        cpa16(sbuf + C2_BH + (row * C2_RS + cg) * 2, &g_wh[g]);
        cpa16(sbuf + C2_BL + (row * C2_RS + cg) * 2, &g_wl[g]);
    }
}

__global__ __launch_bounds__(256, 1) void kC2() {
    extern __shared__ char smem[];
    const uint32_t sb = smem_u32(smem);
    const int tid = threadIdx.x;
    const int wid = tid >> 5;
    const int L   = tid & 31;
    const int m0  = blockIdx.x * 128;
    const int n0  = blockIdx.y * 64;
    const int k0  = blockIdx.z * 256;

    const int wm = wid & 1;
    const int wn = wid >> 1;

    float acc[4][2][4];
#pragma unroll
    for (int mi = 0; mi < 4; mi++)
#pragma unroll
        for (int ni = 0; ni < 2; ni++)
#pragma unroll
            for (int e = 0; e < 4; e++) acc[mi][ni][e] = 0.f;

    const int a_row = (L & 7) + ((L >> 3) & 1) * 8;
    const int a_ch  = (L >> 4) * 8;
    const int b_row = (L & 7) + (L >> 4) * 8;
    const int b_ch  = ((L >> 3) & 1) * 8;

    c2_stage(sb, m0, n0, k0, tid);
    CPA_COMMIT();

#pragma unroll
    for (int stage = 0; stage < 4; ++stage) {
        if (stage < 3) {
            c2_stage(sb + ((stage + 1) & 1) * C2_BUF, m0, n0, k0 + (stage + 1) * 64, tid);
            CPA_COMMIT();
            CPA_WAIT1();
        } else {
            CPA_WAIT0();
        }
        __syncthreads();
        uint32_t bufb = sb + (stage & 1) * C2_BUF;

#pragma unroll
        for (int ks = 0; ks < 4; ++ks) {
            int kc = ks * 16;
            uint32_t bhf[4], blf[4];
            {
                uint32_t off = (uint32_t)((wn * 16 + b_row) * C2_RS + kc + b_ch) * 2;
                ldm_x4(bhf, bufb + C2_BH + off);
                ldm_x4(blf, bufb + C2_BL + off);
            }
#pragma unroll
            for (int mi = 0; mi < 4; mi++) {
                uint32_t ah[4], al[4];
                uint32_t off = (uint32_t)((wm * 64 + mi * 16 + a_row) * C2_RS + kc + a_ch) * 2;
                ldm_x4(ah, bufb + C2_AH + off);
                ldm_x4(al, bufb + C2_AL + off);
#pragma unroll
                for (int ni = 0; ni < 2; ni++) {
                    mma16816(acc[mi][ni], ah, bhf[ni * 2], bhf[ni * 2 + 1]);
                    mma16816(acc[mi][ni], ah, blf[ni * 2], blf[ni * 2 + 1]);
                    mma16816(acc[mi][ni], al, bhf[ni * 2], bhf[ni * 2 + 1]);
                }
            }
        }
        __syncthreads();
    }

    float* pb = g_part + (size_t)blockIdx.z * NR * OD;
#pragma unroll
    for (int mi = 0; mi < 4; mi++) {
        int m_lo = m0 + wm * 64 + mi * 16 + (L >> 2);
        int nn   = n0 + wn * 16 + (L & 3) * 2;
#pragma unroll
        for (int ni = 0; ni < 2; ni++) {
            int nc = nn + ni * 8;
            if (m_lo < NR)
                *(float2*)&pb[(size_t)m_lo * OD + nc] =
                    make_float2(acc[mi][ni][0], acc[mi][ni][1]);
            if (m_lo + 8 < NR)
                *(float2*)&pb[(size_t)(m_lo + 8) * OD + nc] =
                    make_float2(acc[mi][ni][2], acc[mi][ni][3]);
        }
    }
}

// ---------------------------------------------------------------------------
// Kernel C3: reduce split-K partials + bias + final row L2 norm -> output
// ---------------------------------------------------------------------------
__global__ __launch_bounds__(256) void kC3(const float* __restrict__ mb,
                                           float* __restrict__ out) {
    __shared__ float red[8];
    const int rrow = blockIdx.x;
    const int tid  = threadIdx.x;
    float s = mb[tid];
#pragma unroll
    for (int ks = 0; ks < KSP; ks++)
        s += g_part[((size_t)ks * NR + rrow) * OD + tid];
    float sq = s * s;
#pragma unroll
    for (int off = 16; off > 0; off >>= 1)
        sq += __shfl_xor_sync(0xffffffffu, sq, off);
    if ((tid & 31) == 0) red[tid >> 5] = sq;
    __syncthreads();
    float tot = 0.f;
#pragma unroll
    for (int i = 0; i < 8; i++) tot += red[i];
    out[(size_t)rrow * OD + tid] = s / fmaxf(sqrtf(tot), 1e-12f);
}

extern "C" void kernel_launch(void* const* d_in, const int* in_sizes, int n_in,
                              void* d_out, int out_size) {
    (void)in_sizes; (void)n_in; (void)out_size;
    const float* x       = (const float*)d_in[0];
    const float* centers = (const float*)d_in[1];
    const float* cw      = (const float*)d_in[2];
    const float* cb      = (const float*)d_in[3];
    const float* mw      = (const float*)d_in[4];
    const float* mb      = (const float*)d_in[5];
    float* out = (float*)d_out;

    cudaFuncSetAttribute(kF, cudaFuncAttributeMaxDynamicSharedMemorySize, F_SMEM);
    cudaFuncSetAttribute(kC2, cudaFuncAttributeMaxDynamicSharedMemorySize, C2_SMEM);

    kW<<<OD * KD / (256 * 8), 256>>>(mw);
    kF<<<NB * NCH, 320, F_SMEM>>>(x, cw, cb);
    kC1<<<NB * KC * 2 / 8, 256>>>(centers);
    kC2<<<dim3(2, 4, KSP), 256, C2_SMEM>>>();
    kC3<<<NR, 256>>>(mb, out);
}